// round 15
// baseline (speedup 1.0000x reference)
#include <cuda_runtime.h>
#include <cuda_fp16.h>
#include <cstdint>

// Problem constants
#define BB 4
#define SS 4096
#define FF 1024
#define HH 16
#define DKk 64
#define RR 32
#define CHUNK 128
#define NCH (SS / CHUNK)   // 32
#define MM (BB * SS)       // 16384

// GEMM tiling: 128x128 tile, K-chunks of 64
#define Bb_M 128
#define Bb_N 128
#define NCHUNKS (FF / 64)          // 8 K-chunks of 64
#define STG 32768                  // A 16K | B 16K per stage
#define NSTAGES 3
#define GEMM_SMEM (NSTAGES * STG)  // 96 KB

// ---------------------------------------------------------------------------
// Scratch (device globals; no allocation allowed)
// ---------------------------------------------------------------------------
__device__ __half g_pq[MM * FF];   // projected q (fp16)
__device__ __half g_pk[MM * FF];   // projected k (fp16)
__device__ float g_qc[BB * NCH * FF];   // per-chunk column sums (incl bias)
__device__ float g_kc[BB * NCH * FF];
__device__ __half g_qh[MM * FF];   // fp16 query input
__device__ __half g_kh[MM * FF];   // fp16 key input
__device__ __half g_xh[MM * FF];   // pre-output activation (fp16)
__device__ __half g_wqh[FF * FF];
__device__ __half g_wkh[FF * FF];
__device__ __half g_woh[FF * FF];
__device__ __half g_meh[HH * DKk * DKk];
__device__ __half g_mrh[HH * DKk * DKk];

struct GemmArgs {
    const __half* A;
    const __half* B;
    const float* bias;
    __half* Ch;     // used when HALFOUT
    float* Cf;      // used when !HALFOUT
    float* cs;      // optional per-chunk column sums
};

// ---------------------------------------------------------------------------
// PTX helpers (plain sm_80+ instructions: ldmatrix / mma.sync / cp.async)
// ---------------------------------------------------------------------------
__device__ __forceinline__ uint32_t smem_u32(const void* p) {
    uint32_t a;
    asm("{ .reg .u64 t; cvta.to.shared.u64 t, %1; cvt.u32.u64 %0, t; }" : "=r"(a) : "l"(p));
    return a;
}

__device__ __forceinline__ void cpasync16(uint32_t s, const void* g) {
    asm volatile("cp.async.cg.shared.global [%0], [%1], 16;" :: "r"(s), "l"(g));
}
__device__ __forceinline__ void cp_commit() {
    asm volatile("cp.async.commit_group;" ::: "memory");
}
template <int N>
__device__ __forceinline__ void cp_wait() {
    asm volatile("cp.async.wait_group %0;" :: "n"(N) : "memory");
}

__device__ __forceinline__ void ldsm4(uint32_t* r, uint32_t addr) {
    asm volatile("ldmatrix.sync.aligned.m8n8.x4.shared.b16 {%0,%1,%2,%3}, [%4];"
                 : "=r"(r[0]), "=r"(r[1]), "=r"(r[2]), "=r"(r[3]) : "r"(addr));
}

__device__ __forceinline__ void mma16816(float* c, const uint32_t* a, const uint32_t* b) {
    asm volatile(
        "mma.sync.aligned.m16n8k16.row.col.f32.f16.f16.f32 "
        "{%0,%1,%2,%3}, {%4,%5,%6,%7}, {%8,%9}, {%0,%1,%2,%3};"
        : "+f"(c[0]), "+f"(c[1]), "+f"(c[2]), "+f"(c[3])
        : "r"(a[0]), "r"(a[1]), "r"(a[2]), "r"(a[3]), "r"(b[0]), "r"(b[1]));
}

// ---------------------------------------------------------------------------
// All fp32->fp16 converts in ONE launch. Flat-grid job split (compile-time).
// ---------------------------------------------------------------------------
#define CV_ACT (MM * FF / 4 / 256)   // 16384 blocks per activation
#define CV_W   (FF * FF / 4 / 256)   // 1024 blocks per weight
#define CV_TOTAL (2 * CV_ACT + 3 * CV_W)
__global__ void cvt_all_kernel(const float* __restrict__ q, const float* __restrict__ k,
                               const float* __restrict__ wq, const float* __restrict__ wk,
                               const float* __restrict__ wo)
{
    int bidx = blockIdx.x;
    const float* src; __half* dst; int i0;
    if (bidx < CV_ACT)                     { src = q;  dst = g_qh;  i0 = bidx; }
    else if (bidx < 2 * CV_ACT)            { src = k;  dst = g_kh;  i0 = bidx - CV_ACT; }
    else if (bidx < 2 * CV_ACT + CV_W)     { src = wq; dst = g_wqh; i0 = bidx - 2 * CV_ACT; }
    else if (bidx < 2 * CV_ACT + 2 * CV_W) { src = wk; dst = g_wkh; i0 = bidx - 2 * CV_ACT - CV_W; }
    else                                   { src = wo; dst = g_woh; i0 = bidx - 2 * CV_ACT - 2 * CV_W; }
    int i = i0 * 256 + threadIdx.x;
    float4 v = ((const float4*)src)[i];
    ((__half2*)dst)[2 * i]     = __floats2half2_rn(v.x, v.y);
    ((__half2*)dst)[2 * i + 1] = __floats2half2_rn(v.z, v.w);
}

// ---------------------------------------------------------------------------
// Precompute per-head Me = We@Wc1^T, Mr = Wr@Wc2^T (stored [n][k], fp16 hi)
// ---------------------------------------------------------------------------
__global__ void make_m_kernel(const float* __restrict__ We, const float* __restrict__ Wr,
                              const float* __restrict__ Wc)
{
    int h = blockIdx.x;
    __shared__ float sWe[DKk * RR], sWr[DKk * RR], sWc[DKk * 2 * RR];
    for (int i = threadIdx.x; i < DKk * RR; i += 256) {
        sWe[i] = We[h * DKk * RR + i];
        sWr[i] = Wr[h * DKk * RR + i];
    }
    for (int i = threadIdx.x; i < DKk * 2 * RR; i += 256) sWc[i] = Wc[i];
    __syncthreads();
    for (int idx = threadIdx.x; idx < DKk * DKk; idx += 256) {
        int n = idx >> 6, kk = idx & 63;
        float me = 0.f, mr = 0.f;
#pragma unroll
        for (int e = 0; e < RR; e++) {
            me += sWe[kk * RR + e] * sWc[n * (2 * RR) + e];
            mr += sWr[kk * RR + e] * sWc[n * (2 * RR) + RR + e];
        }
        g_meh[h * 4096 + idx] = __float2half_rn(me);
        g_mrh[h * 4096 + idx] = __float2half_rn(mr);
    }
}

// ---------------------------------------------------------------------------
// HMMA GEMM: C[m,n] = bias[n] + sum_k A[m,k]*B[n,k], single fp16 pass.
// 128x128 tile, K chunks of 64 (8 chunks), 3-stage cp.async pipe, 2 CTAs/SM.
// Stage: A 128x128B | B 128x128B, swizzle seg ^= row&7 (8 segs per row).
// blockIdx.z selects arg set (fused q/k launch). HALFOUT: write fp16.
// Optional colsum: per-128-row-chunk column sums of final C (incl bias).
// ---------------------------------------------------------------------------
template <bool HALFOUT>
__global__ __launch_bounds__(256, 2)
void gemm_hmma(GemmArgs g0, GemmArgs g1)
{
    const GemmArgs g = blockIdx.z ? g1 : g0;
    extern __shared__ char smem[];
    __shared__ float scs[2][128];
    const uint32_t sbase = smem_u32(smem);
    const int tid = threadIdx.x;
    const int wid = tid >> 5, lane = tid & 31;
    const int m0 = blockIdx.y * Bb_M;
    const int n0 = blockIdx.x * Bb_N;
    const int wm = (wid & 1) * 64;
    const int wn = (wid >> 1) * 32;

    const char* pA = (const char*)g.A + (size_t)m0 * (FF * 2);
    const char* pB = (const char*)g.B + (size_t)n0 * (FF * 2);

    // gmem->smem: thread handles one row (tid>>1), 4 of 8 16B segs per array
    const int lrow = tid >> 1;
    const int lsegb = (tid & 1) * 4;

    auto load_stage = [&](int c, int buf) {
        uint32_t sb = sbase + buf * STG;
        size_t kb = (size_t)c * 128;      // 64 fp16 = 128 bytes along K
#pragma unroll
        for (int j = 0; j < 4; j++) {
            int seg = lsegb + j;
            uint32_t soff = lrow * 128 + ((seg ^ (lrow & 7)) << 4);
            size_t goff = (size_t)lrow * (FF * 2) + kb + seg * 16;
            cpasync16(sb + soff,         pA + goff);
            cpasync16(sb + 16384 + soff, pB + goff);
        }
        cp_commit();
    };

    float acc[4][4][4];
#pragma unroll
    for (int i = 0; i < 4; i++)
#pragma unroll
        for (int j = 0; j < 4; j++)
#pragma unroll
            for (int e = 0; e < 4; e++) acc[i][j][e] = 0.0f;

    int arow[4];
#pragma unroll
    for (int mf = 0; mf < 4; mf++)
        arow[mf] = wm + mf * 16 + (lane & 15);
    int brow[2];
#pragma unroll
    for (int ng = 0; ng < 2; ng++)
        brow[ng] = wn + ng * 16 + ((lane >> 4) << 3) + (lane & 7);

    load_stage(0, 0);
    load_stage(1, 1);

    for (int c = 0; c < NCHUNKS; c++) {
        if (c + 1 < NCHUNKS) cp_wait<1>(); else cp_wait<0>();
        __syncthreads();
        if (c + 2 < NCHUNKS) load_stage(c + 2, (c + 2) % NSTAGES);

        uint32_t sb = sbase + (c % NSTAGES) * STG;
#pragma unroll
        for (int ks = 0; ks < 4; ks++) {
            uint32_t ah[4][4], bf[2][4];
#pragma unroll
            for (int mf = 0; mf < 4; mf++) {
                int seg = ks * 2 + (lane >> 4);
                uint32_t off = arow[mf] * 128 + ((seg ^ (arow[mf] & 7)) << 4);
                ldsm4(ah[mf], sb + off);
            }
#pragma unroll
            for (int ng = 0; ng < 2; ng++) {
                int seg = ks * 2 + ((lane & 15) >> 3);
                uint32_t off = brow[ng] * 128 + ((seg ^ (brow[ng] & 7)) << 4);
                ldsm4(bf[ng], sb + 16384 + off);
            }
#pragma unroll
            for (int mf = 0; mf < 4; mf++)
#pragma unroll
                for (int nf = 0; nf < 4; nf++)
                    mma16816(acc[mf][nf], ah[mf], &bf[nf >> 1][(nf & 1) * 2]);
        }
    }

    // Epilogue: + bias, store (fp16 or fp32)
#pragma unroll
    for (int mf = 0; mf < 4; mf++) {
        int r0 = m0 + wm + mf * 16 + (lane >> 2);
#pragma unroll
        for (int nf = 0; nf < 4; nf++) {
            int col = n0 + wn + nf * 8 + (lane & 3) * 2;
            float bx = g.bias[col], by = g.bias[col + 1];
            float v00 = acc[mf][nf][0] + bx, v01 = acc[mf][nf][1] + by;
            float v10 = acc[mf][nf][2] + bx, v11 = acc[mf][nf][3] + by;
            if (HALFOUT) {
                *(__half2*)&g.Ch[(size_t)r0 * FF + col]       = __floats2half2_rn(v00, v01);
                *(__half2*)&g.Ch[(size_t)(r0 + 8) * FF + col] = __floats2half2_rn(v10, v11);
            } else {
                *(float2*)&g.Cf[(size_t)r0 * FF + col]       = make_float2(v00, v01);
                *(float2*)&g.Cf[(size_t)(r0 + 8) * FF + col] = make_float2(v10, v11);
            }
        }
    }

    // Optional: per-chunk column sums (this CTA's 128 rows == one (b,chunk))
    if (g.cs != nullptr) {
        float cs0[4], cs1[4];
#pragma unroll
        for (int nf = 0; nf < 4; nf++) {
            cs0[nf] = 0.f; cs1[nf] = 0.f;
#pragma unroll
            for (int mf = 0; mf < 4; mf++) {
                cs0[nf] += acc[mf][nf][0] + acc[mf][nf][2];
                cs1[nf] += acc[mf][nf][1] + acc[mf][nf][3];
            }
        }
#pragma unroll
        for (int o = 16; o >= 4; o >>= 1)
#pragma unroll
            for (int nf = 0; nf < 4; nf++) {
                cs0[nf] += __shfl_xor_sync(0xffffffffu, cs0[nf], o);
                cs1[nf] += __shfl_xor_sync(0xffffffffu, cs1[nf], o);
            }
        if (lane < 4) {
#pragma unroll
            for (int nf = 0; nf < 4; nf++) {
                scs[wid & 1][wn + nf * 8 + lane * 2]     = cs0[nf];
                scs[wid & 1][wn + nf * 8 + lane * 2 + 1] = cs1[nf];
            }
        }
        __syncthreads();
        if (tid < 128) {
            float tot = scs[0][tid] + scs[1][tid] + 128.0f * g.bias[n0 + tid];
            g.cs[(m0 >> 7) * FF + n0 + tid] = tot;
        }
    }
}

// ---------------------------------------------------------------------------
// Fused scan + norm + xgemm: per (b,h,chunk=128 rows). 4 CTAs/SM.
//   0. (overlapped with loads) sum chunk colsums 0..ch-1 -> smem prefix
//   1. load pq/pk tile (fp16) + Me/Mr into smem via cp.async
//   2a. serial cumsum + running-average in smem (shfl-free)
//   2b. per-ROW L2-normalize: one thread per row, two passes
//   3. x = qn@Me + kn@Mr + bc via HMMA; write fp16 x
// 256 threads. SMEM: sQ 16K | sK 16K | Me 8K | Mr 8K = 48KB.
// ---------------------------------------------------------------------------
#define XG_SMEM 49152
__global__ __launch_bounds__(256, 4)
void xgemm_kernel(const float* __restrict__ bc)
{
    extern __shared__ char smem[];
    __shared__ float swsum[8][64];
    __shared__ float spfx[2][64];
    const uint32_t sbase = smem_u32(smem);
    const int tid = threadIdx.x;
    const int wid = tid >> 5, lane = tid & 31;
    const int ch = blockIdx.x;
    const int s0base = ch * 128;
    const int b = blockIdx.y >> 4;
    const int h = blockIdx.y & 15;

    // ---- load phase (async) ----
    {
        const char* gq = (const char*)g_pq + (((size_t)(b * SS + s0base)) * FF + h * DKk) * 2;
        const char* gk = (const char*)g_pk + (((size_t)(b * SS + s0base)) * FF + h * DKk) * 2;
        int row = tid >> 1;                 // 0..127
        int sh = (tid & 1) * 4;
#pragma unroll
        for (int s = 0; s < 4; s++) {
            int seg = sh + s;
            uint32_t soff = row * 128 + ((seg ^ (row & 7)) << 4);
            size_t goff = (size_t)row * (FF * 2) + seg * 16;
            cpasync16(sbase + soff,         gq + goff);
            cpasync16(sbase + 16384 + soff, gk + goff);
        }
        const char* srcs[2] = {(const char*)(g_meh + h * 4096), (const char*)(g_mrh + h * 4096)};
#pragma unroll
        for (int j = 0; j < 4; j++) {
            int i = tid + j * 256;          // 0..1023
            int m = i >> 9;
            int r = (i >> 3) & 63;
            int seg = i & 7;
            uint32_t soff = r * 128 + ((seg ^ (r & 7)) << 4);
            cpasync16(sbase + 32768 + m * 8192 + soff, srcs[m] + r * 128 + seg * 16);
        }
        cp_commit();
    }

    // ---- phase 0 (overlapped): chunk prefix from colsums ----
    if (tid < 128) {
        int side = tid >> 6;            // 0: q, 1: k
        int col = tid & 63;
        const float* pc = side ? g_kc : g_qc;
        float s = 0.f;
        for (int c = 0; c < ch; c++)
            s += pc[(b * NCH + c) * FF + h * DKk + col];
        spfx[side][col] = s;
    }

    cp_wait<0>();
    __syncthreads();

    // ---- phase 2a: serial cumsum + running average (shfl-free) ----
    {
        const int isK = wid >> 2;           // warps 0-3: q, 4-7: k
        const int blk = wid & 3;            // 32-row sub-block
        char* tb = smem + isK * 16384;
        const int segc = lane >> 2;
        const int ib = (lane & 3) * 4;

        float s0 = 0.f, s1 = 0.f;
#pragma unroll 8
        for (int i = 0; i < 32; i++) {
            int r = blk * 32 + i;
            float2 f = __half22float2(*(__half2*)(tb + r * 128 + ((segc ^ (r & 7)) << 4) + ib));
            s0 += f.x; s1 += f.y;
        }
        swsum[wid][2 * lane] = s0;
        swsum[wid][2 * lane + 1] = s1;
        __syncthreads();

        float p0 = spfx[isK][2 * lane];
        float p1 = spfx[isK][2 * lane + 1];
        for (int w = isK * 4; w < wid; w++) {
            p0 += swsum[w][2 * lane];
            p1 += swsum[w][2 * lane + 1];
        }

        int nbase = ch * CHUNK + blk * 32;
        for (int i = 0; i < 32; i++) {
            int r = blk * 32 + i;
            char* p = tb + r * 128 + ((segc ^ (r & 7)) << 4) + ib;
            float2 f = __half22float2(*(__half2*)p);
            p0 += f.x; p1 += f.y;
            float inv = 1.0f / (float)(nbase + i + 1);
            *(__half2*)p = __floats2half2_rn(p0 * inv, p1 * inv);
        }
    }
    __syncthreads();

    // ---- phase 2b: per-row L2 normalization (one thread/row, two passes) ----
    {
        const int side = tid >> 7;          // 0: q, 1: k
        const int r = tid & 127;
        char* tb = smem + side * 16384 + r * 128;
        const int sx = (r & 7) << 4;
        float nrm = 0.f;
#pragma unroll
        for (int seg = 0; seg < 8; seg++) {
            uint4 v = *(uint4*)(tb + ((seg << 4) ^ sx));
            const __half2* hp = (const __half2*)&v;
#pragma unroll
            for (int j = 0; j < 4; j++) {
                float2 f = __half22float2(hp[j]);
                nrm = fmaf(f.x, f.x, fmaf(f.y, f.y, nrm));
            }
        }
        float rs = 1.0f / fmaxf(sqrtf(nrm), 1e-12f);
#pragma unroll
        for (int seg = 0; seg < 8; seg++) {
            uint4 v = *(uint4*)(tb + ((seg << 4) ^ sx));
            __half2* hp = (__half2*)&v;
#pragma unroll
            for (int j = 0; j < 4; j++) {
                float2 f = __half22float2(hp[j]);
                hp[j] = __floats2half2_rn(f.x * rs, f.y * rs);
            }
            *(uint4*)(tb + ((seg << 4) ^ sx)) = v;
        }
    }
    __syncthreads();

    // ---- mma phase: 8 warps, warp tile 16 rows x 64 cols ----
    const int wm = wid * 16;
    float acc[8][4];
#pragma unroll
    for (int j = 0; j < 8; j++)
#pragma unroll
        for (int e = 0; e < 4; e++) acc[j][e] = 0.0f;

#pragma unroll
    for (int part = 0; part < 2; part++) {
        uint32_t aBase = sbase + part * 16384;
        uint32_t hBase = sbase + 32768 + part * 8192;
#pragma unroll
        for (int ks = 0; ks < 4; ks++) {
            uint32_t a[4], bhf[4][4];
            {
                int arow = wm + (lane & 15);
                int seg = ks * 2 + (lane >> 4);
                ldsm4(a, aBase + arow * 128 + ((seg ^ (arow & 7)) << 4));
            }
#pragma unroll
            for (int ng = 0; ng < 4; ng++) {
                int brow = ng * 16 + ((lane >> 4) << 3) + (lane & 7);
                int seg = ks * 2 + ((lane & 15) >> 3);
                uint32_t off = brow * 128 + ((seg ^ (brow & 7)) << 4);
                ldsm4(bhf[ng], hBase + off);
            }
#pragma unroll
            for (int nf = 0; nf < 8; nf++)
                mma16816(acc[nf], a, &bhf[nf >> 1][(nf & 1) * 2]);
        }
    }

    // ---- epilogue ----
    {
        int s0r = s0base + wm + (lane >> 2);
#pragma unroll
        for (int nf = 0; nf < 8; nf++) {
            int col = nf * 8 + (lane & 3) * 2;
            float b0 = bc[col], b1 = bc[col + 1];
            size_t o0 = ((size_t)(b * SS + s0r)) * FF + h * DKk + col;
            size_t o1 = o0 + (size_t)8 * FF;
            *(__half2*)&g_xh[o0] = __floats2half2_rn(acc[nf][0] + b0, acc[nf][1] + b1);
            *(__half2*)&g_xh[o1] = __floats2half2_rn(acc[nf][2] + b0, acc[nf][3] + b1);
        }
    }
}

// ---------------------------------------------------------------------------
// Launch
// ---------------------------------------------------------------------------
extern "C" void kernel_launch(void* const* d_in, const int* in_sizes, int n_in,
                              void* d_out, int out_size)
{
    const float* query = (const float*)d_in[0];
    const float* key   = (const float*)d_in[1];
    const float* Wq = (const float*)d_in[4];
    const float* bq = (const float*)d_in[5];
    const float* Wk = (const float*)d_in[6];
    const float* bk = (const float*)d_in[7];
    const float* We = (const float*)d_in[10];
    const float* Wr = (const float*)d_in[11];
    const float* Wc = (const float*)d_in[13];
    const float* bc = (const float*)d_in[14];
    const float* Wo = (const float*)d_in[15];
    const float* bo = (const float*)d_in[16];
    float* out = (float*)d_out;

    void *ppq, *ppk, *pqc, *pkc, *pqh, *pkh, *pxh;
    void *pwqh, *pwkh, *pwoh;
    cudaGetSymbolAddress(&ppq, g_pq);
    cudaGetSymbolAddress(&ppk, g_pk);
    cudaGetSymbolAddress(&pqc, g_qc);
    cudaGetSymbolAddress(&pkc, g_kc);
    cudaGetSymbolAddress(&pqh, g_qh);
    cudaGetSymbolAddress(&pkh, g_kh);
    cudaGetSymbolAddress(&pxh, g_xh);
    cudaGetSymbolAddress(&pwqh, g_wqh);
    cudaGetSymbolAddress(&pwkh, g_wkh);
    cudaGetSymbolAddress(&pwoh, g_woh);

    cudaFuncSetAttribute((void*)gemm_hmma<true>,
                         cudaFuncAttributeMaxDynamicSharedMemorySize, GEMM_SMEM);
    cudaFuncSetAttribute((void*)gemm_hmma<false>,
                         cudaFuncAttributeMaxDynamicSharedMemorySize, GEMM_SMEM);
    cudaFuncSetAttribute((void*)xgemm_kernel,
                         cudaFuncAttributeMaxDynamicSharedMemorySize, XG_SMEM);

    // 0. converts (activations + weights, one launch) + make_m (smem-staged)
    cvt_all_kernel<<<CV_TOTAL, 256>>>(query, key, Wq, Wk, Wo);
    make_m_kernel<<<HH, 256>>>(We, Wr, Wc);

    // 1. q + k projections fused in one launch (fp16 out + chunk column sums)
    GemmArgs aq{(const __half*)pqh, (const __half*)pwqh, bq, (__half*)ppq, nullptr, (float*)pqc};
    GemmArgs ak{(const __half*)pkh, (const __half*)pwkh, bk, (__half*)ppk, nullptr, (float*)pkc};
    gemm_hmma<true><<<dim3(FF / Bb_N, MM / Bb_M, 2), 256, GEMM_SMEM>>>(aq, ak);

    // 2. fused chunk-prefix + norm + x = qn@Me + kn@Mr + bc (batched HMMA)
    xgemm_kernel<<<dim3(NCH, BB * HH), 256, XG_SMEM>>>(bc);

    // 3. output projection (single-pass fp16 HMMA, fp32 out, 128x128 tiles)
    GemmArgs ao{(const __half*)pxh, (const __half*)pwoh, bo, nullptr, out, nullptr};
    gemm_hmma<false><<<dim3(FF / Bb_N, MM / Bb_M, 1), 256, GEMM_SMEM>>>(ao, ao);
}

// round 16
// speedup vs baseline: 1.2052x; 1.2052x over previous
#include <cuda_runtime.h>
#include <cuda_fp16.h>
#include <cstdint>

// Problem constants
#define BB 4
#define SS 4096
#define FF 1024
#define HH 16
#define DKk 64
#define RR 32
#define CHUNK 128
#define NCH (SS / CHUNK)   // 32
#define MM (BB * SS)       // 16384

// GEMM tiling
#define Bb_M 128
#define Bb_N 128
#define NCHUNKS (FF / 32)          // 16 K-chunks of 32
#define STG 16384                  // A 8K | B 8K per stage
#define NSTAGES 4
#define GEMM_SMEM (NSTAGES * STG)  // 64 KB

// ---------------------------------------------------------------------------
// Scratch (device globals; no allocation allowed)
// ---------------------------------------------------------------------------
__device__ __half g_pq[MM * FF];   // projected q (fp16)
__device__ __half g_pk[MM * FF];   // projected k (fp16)
__device__ float g_qc[BB * NCH * FF];   // per-chunk column sums (incl bias)
__device__ float g_kc[BB * NCH * FF];
__device__ __half g_qh[MM * FF];   // fp16 query input
__device__ __half g_kh[MM * FF];   // fp16 key input
__device__ __half g_xh[MM * FF];   // pre-output activation (fp16)
__device__ __half g_wqh[FF * FF];
__device__ __half g_wkh[FF * FF];
__device__ __half g_woh[FF * FF];
__device__ __half g_meh[HH * DKk * DKk];
__device__ __half g_mrh[HH * DKk * DKk];

struct GemmArgs {
    const __half* A;
    const __half* B;
    const float* bias;
    __half* Ch;     // used when HALFOUT
    float* Cf;      // used when !HALFOUT
    float* cs;      // optional per-chunk column sums
};

// ---------------------------------------------------------------------------
// PTX helpers (plain sm_80+ instructions: ldmatrix / mma.sync / cp.async)
// ---------------------------------------------------------------------------
__device__ __forceinline__ uint32_t smem_u32(const void* p) {
    uint32_t a;
    asm("{ .reg .u64 t; cvta.to.shared.u64 t, %1; cvt.u32.u64 %0, t; }" : "=r"(a) : "l"(p));
    return a;
}

__device__ __forceinline__ void cpasync16(uint32_t s, const void* g) {
    asm volatile("cp.async.cg.shared.global [%0], [%1], 16;" :: "r"(s), "l"(g));
}
__device__ __forceinline__ void cp_commit() {
    asm volatile("cp.async.commit_group;" ::: "memory");
}
template <int N>
__device__ __forceinline__ void cp_wait() {
    asm volatile("cp.async.wait_group %0;" :: "n"(N) : "memory");
}

__device__ __forceinline__ void ldsm4(uint32_t* r, uint32_t addr) {
    asm volatile("ldmatrix.sync.aligned.m8n8.x4.shared.b16 {%0,%1,%2,%3}, [%4];"
                 : "=r"(r[0]), "=r"(r[1]), "=r"(r[2]), "=r"(r[3]) : "r"(addr));
}

__device__ __forceinline__ void mma16816(float* c, const uint32_t* a, const uint32_t* b) {
    asm volatile(
        "mma.sync.aligned.m16n8k16.row.col.f32.f16.f16.f32 "
        "{%0,%1,%2,%3}, {%4,%5,%6,%7}, {%8,%9}, {%0,%1,%2,%3};"
        : "+f"(c[0]), "+f"(c[1]), "+f"(c[2]), "+f"(c[3])
        : "r"(a[0]), "r"(a[1]), "r"(a[2]), "r"(a[3]), "r"(b[0]), "r"(b[1]));
}

// ---------------------------------------------------------------------------
// All fp32->fp16 converts in ONE launch. Flat-grid job split (compile-time).
// ---------------------------------------------------------------------------
#define CV_ACT (MM * FF / 4 / 256)   // 16384 blocks per activation
#define CV_W   (FF * FF / 4 / 256)   // 1024 blocks per weight
#define CV_TOTAL (2 * CV_ACT + 3 * CV_W)
__global__ void cvt_all_kernel(const float* __restrict__ q, const float* __restrict__ k,
                               const float* __restrict__ wq, const float* __restrict__ wk,
                               const float* __restrict__ wo)
{
    int bidx = blockIdx.x;
    const float* src; __half* dst; int i0;
    if (bidx < CV_ACT)                     { src = q;  dst = g_qh;  i0 = bidx; }
    else if (bidx < 2 * CV_ACT)            { src = k;  dst = g_kh;  i0 = bidx - CV_ACT; }
    else if (bidx < 2 * CV_ACT + CV_W)     { src = wq; dst = g_wqh; i0 = bidx - 2 * CV_ACT; }
    else if (bidx < 2 * CV_ACT + 2 * CV_W) { src = wk; dst = g_wkh; i0 = bidx - 2 * CV_ACT - CV_W; }
    else                                   { src = wo; dst = g_woh; i0 = bidx - 2 * CV_ACT - 2 * CV_W; }
    int i = i0 * 256 + threadIdx.x;
    float4 v = ((const float4*)src)[i];
    ((__half2*)dst)[2 * i]     = __floats2half2_rn(v.x, v.y);
    ((__half2*)dst)[2 * i + 1] = __floats2half2_rn(v.z, v.w);
}

// ---------------------------------------------------------------------------
// Precompute per-head Me = We@Wc1^T, Mr = Wr@Wc2^T (stored [n][k], fp16 hi)
// smem-staged (fast, coalesced).
// ---------------------------------------------------------------------------
__global__ void make_m_kernel(const float* __restrict__ We, const float* __restrict__ Wr,
                              const float* __restrict__ Wc)
{
    int h = blockIdx.x;
    __shared__ float sWe[DKk * RR], sWr[DKk * RR], sWc[DKk * 2 * RR];
    for (int i = threadIdx.x; i < DKk * RR; i += 256) {
        sWe[i] = We[h * DKk * RR + i];
        sWr[i] = Wr[h * DKk * RR + i];
    }
    for (int i = threadIdx.x; i < DKk * 2 * RR; i += 256) sWc[i] = Wc[i];
    __syncthreads();
    for (int idx = threadIdx.x; idx < DKk * DKk; idx += 256) {
        int n = idx >> 6, kk = idx & 63;
        float me = 0.f, mr = 0.f;
#pragma unroll
        for (int e = 0; e < RR; e++) {
            me += sWe[kk * RR + e] * sWc[n * (2 * RR) + e];
            mr += sWr[kk * RR + e] * sWc[n * (2 * RR) + RR + e];
        }
        g_meh[h * 4096 + idx] = __float2half_rn(me);
        g_mrh[h * 4096 + idx] = __float2half_rn(mr);
    }
}

// ---------------------------------------------------------------------------
// HMMA GEMM: C[m,n] = bias[n] + sum_k A[m,k]*B[n,k], single fp16 pass.
// 128x128 tile, K chunks of 32, 4-stage cp.async pipe, 2 CTAs/SM.
// blockIdx.z selects arg set (fused q/k launch). HALFOUT: write fp16.
// Optional colsum: per-128-row-chunk column sums of final C (incl bias).
// ---------------------------------------------------------------------------
template <bool HALFOUT>
__global__ __launch_bounds__(256, 2)
void gemm_hmma(GemmArgs g0, GemmArgs g1)
{
    const GemmArgs g = blockIdx.z ? g1 : g0;
    extern __shared__ char smem[];
    __shared__ float scs[2][128];
    const uint32_t sbase = smem_u32(smem);
    const int tid = threadIdx.x;
    const int wid = tid >> 5, lane = tid & 31;
    const int m0 = blockIdx.y * Bb_M;
    const int n0 = blockIdx.x * Bb_N;
    const int wm = (wid & 1) * 64;
    const int wn = (wid >> 1) * 32;

    const char* pA = (const char*)g.A + (size_t)m0 * (FF * 2);
    const char* pB = (const char*)g.B + (size_t)n0 * (FF * 2);

    const int lrow0 = tid >> 2;
    const int lseg = tid & 3;

    auto load_stage = [&](int c, int buf) {
        uint32_t sb = sbase + buf * STG;
        size_t kb = (size_t)c * 64;
#pragma unroll
        for (int i = 0; i < 2; i++) {
            int row = lrow0 + i * 64;
            uint32_t soff = row * 64 + ((lseg ^ ((row >> 1) & 3)) << 4);
            size_t goff = (size_t)row * (FF * 2) + kb + lseg * 16;
            cpasync16(sb + soff,        pA + goff);
            cpasync16(sb + 8192 + soff, pB + goff);
        }
        cp_commit();
    };

    float acc[4][4][4];
#pragma unroll
    for (int i = 0; i < 4; i++)
#pragma unroll
        for (int j = 0; j < 4; j++)
#pragma unroll
            for (int e = 0; e < 4; e++) acc[i][j][e] = 0.0f;

    int arow[4]; uint32_t aoffbase[4];
#pragma unroll
    for (int mf = 0; mf < 4; mf++) {
        arow[mf] = wm + mf * 16 + (lane & 15);
        aoffbase[mf] = arow[mf] * 64;
    }
    int brow[2];
#pragma unroll
    for (int ng = 0; ng < 2; ng++)
        brow[ng] = wn + ng * 16 + ((lane >> 4) << 3) + (lane & 7);

    load_stage(0, 0);
    load_stage(1, 1);
    load_stage(2, 2);

    for (int c = 0; c < NCHUNKS; c++) {
        if (c + 2 < NCHUNKS) cp_wait<2>();
        else if (c + 1 < NCHUNKS) cp_wait<1>();
        else cp_wait<0>();
        __syncthreads();
        if (c + 3 < NCHUNKS) load_stage(c + 3, (c + 3) % NSTAGES);

        uint32_t sb = sbase + (c % NSTAGES) * STG;
#pragma unroll
        for (int ks = 0; ks < 2; ks++) {
            uint32_t ah[4][4], bf[2][4];
#pragma unroll
            for (int mf = 0; mf < 4; mf++) {
                int seg = ks * 2 + (lane >> 4);
                uint32_t off = aoffbase[mf] + ((seg ^ ((arow[mf] >> 1) & 3)) << 4);
                ldsm4(ah[mf], sb + off);
            }
#pragma unroll
            for (int ng = 0; ng < 2; ng++) {
                int seg = ks * 2 + ((lane & 15) >> 3);
                uint32_t off = brow[ng] * 64 + ((seg ^ ((brow[ng] >> 1) & 3)) << 4);
                ldsm4(bf[ng], sb + 8192 + off);
            }
#pragma unroll
            for (int mf = 0; mf < 4; mf++)
#pragma unroll
                for (int nf = 0; nf < 4; nf++)
                    mma16816(acc[mf][nf], ah[mf], &bf[nf >> 1][(nf & 1) * 2]);
        }
    }

    // Epilogue: + bias, store (fp16 or fp32)
#pragma unroll
    for (int mf = 0; mf < 4; mf++) {
        int r0 = m0 + wm + mf * 16 + (lane >> 2);
#pragma unroll
        for (int nf = 0; nf < 4; nf++) {
            int col = n0 + wn + nf * 8 + (lane & 3) * 2;
            float bx = g.bias[col], by = g.bias[col + 1];
            float v00 = acc[mf][nf][0] + bx, v01 = acc[mf][nf][1] + by;
            float v10 = acc[mf][nf][2] + bx, v11 = acc[mf][nf][3] + by;
            if (HALFOUT) {
                *(__half2*)&g.Ch[(size_t)r0 * FF + col]       = __floats2half2_rn(v00, v01);
                *(__half2*)&g.Ch[(size_t)(r0 + 8) * FF + col] = __floats2half2_rn(v10, v11);
            } else {
                *(float2*)&g.Cf[(size_t)r0 * FF + col]       = make_float2(v00, v01);
                *(float2*)&g.Cf[(size_t)(r0 + 8) * FF + col] = make_float2(v10, v11);
            }
        }
    }

    // Optional: per-chunk column sums (this CTA's 128 rows == one (b,chunk))
    if (g.cs != nullptr) {
        float cs0[4], cs1[4];
#pragma unroll
        for (int nf = 0; nf < 4; nf++) {
            cs0[nf] = 0.f; cs1[nf] = 0.f;
#pragma unroll
            for (int mf = 0; mf < 4; mf++) {
                cs0[nf] += acc[mf][nf][0] + acc[mf][nf][2];
                cs1[nf] += acc[mf][nf][1] + acc[mf][nf][3];
            }
        }
#pragma unroll
        for (int o = 16; o >= 4; o >>= 1)
#pragma unroll
            for (int nf = 0; nf < 4; nf++) {
                cs0[nf] += __shfl_xor_sync(0xffffffffu, cs0[nf], o);
                cs1[nf] += __shfl_xor_sync(0xffffffffu, cs1[nf], o);
            }
        if (lane < 4) {
#pragma unroll
            for (int nf = 0; nf < 4; nf++) {
                scs[wid & 1][wn + nf * 8 + lane * 2]     = cs0[nf];
                scs[wid & 1][wn + nf * 8 + lane * 2 + 1] = cs1[nf];
            }
        }
        __syncthreads();
        if (tid < 128) {
            float tot = scs[0][tid] + scs[1][tid] + 128.0f * g.bias[n0 + tid];
            g.cs[(m0 >> 7) * FF + n0 + tid] = tot;
        }
    }
}

// ---------------------------------------------------------------------------
// Fused scan + norm + xgemm: per (b,h,chunk=128 rows). 4 CTAs/SM.
//   0. (overlapped with loads) sum chunk colsums 0..ch-1 -> smem prefix
//   1. load pq/pk tile (fp16) + Me/Mr into smem via cp.async
//   2a. serial cumsum + running-average in smem (shfl-free)
//   2b. per-ROW L2-normalize: one thread per row, two passes
//   3. x = qn@Me + kn@Mr + bc via HMMA; write fp16 x
// 256 threads. SMEM: sQ 16K | sK 16K | Me 8K | Mr 8K = 48KB.
// ---------------------------------------------------------------------------
#define XG_SMEM 49152
__global__ __launch_bounds__(256, 4)
void xgemm_kernel(const float* __restrict__ bc)
{
    extern __shared__ char smem[];
    __shared__ float swsum[8][64];
    __shared__ float spfx[2][64];
    const uint32_t sbase = smem_u32(smem);
    const int tid = threadIdx.x;
    const int wid = tid >> 5, lane = tid & 31;
    const int ch = blockIdx.x;
    const int s0base = ch * 128;
    const int b = blockIdx.y >> 4;
    const int h = blockIdx.y & 15;

    // ---- load phase (async) ----
    {
        const char* gq = (const char*)g_pq + (((size_t)(b * SS + s0base)) * FF + h * DKk) * 2;
        const char* gk = (const char*)g_pk + (((size_t)(b * SS + s0base)) * FF + h * DKk) * 2;
        int row = tid >> 1;                 // 0..127
        int sh = (tid & 1) * 4;
#pragma unroll
        for (int s = 0; s < 4; s++) {
            int seg = sh + s;
            uint32_t soff = row * 128 + ((seg ^ (row & 7)) << 4);
            size_t goff = (size_t)row * (FF * 2) + seg * 16;
            cpasync16(sbase + soff,         gq + goff);
            cpasync16(sbase + 16384 + soff, gk + goff);
        }
        const char* srcs[2] = {(const char*)(g_meh + h * 4096), (const char*)(g_mrh + h * 4096)};
#pragma unroll
        for (int j = 0; j < 4; j++) {
            int i = tid + j * 256;          // 0..1023
            int m = i >> 9;
            int r = (i >> 3) & 63;
            int seg = i & 7;
            uint32_t soff = r * 128 + ((seg ^ (r & 7)) << 4);
            cpasync16(sbase + 32768 + m * 8192 + soff, srcs[m] + r * 128 + seg * 16);
        }
        cp_commit();
    }

    // ---- phase 0 (overlapped): chunk prefix from colsums ----
    if (tid < 128) {
        int side = tid >> 6;            // 0: q, 1: k
        int col = tid & 63;
        const float* pc = side ? g_kc : g_qc;
        float s = 0.f;
        for (int c = 0; c < ch; c++)
            s += pc[(b * NCH + c) * FF + h * DKk + col];
        spfx[side][col] = s;
    }

    cp_wait<0>();
    __syncthreads();

    // ---- phase 2a: serial cumsum + running average (shfl-free) ----
    {
        const int isK = wid >> 2;           // warps 0-3: q, 4-7: k
        const int blk = wid & 3;            // 32-row sub-block
        char* tb = smem + isK * 16384;
        const int segc = lane >> 2;
        const int ib = (lane & 3) * 4;

        float s0 = 0.f, s1 = 0.f;
#pragma unroll 8
        for (int i = 0; i < 32; i++) {
            int r = blk * 32 + i;
            float2 f = __half22float2(*(__half2*)(tb + r * 128 + ((segc ^ (r & 7)) << 4) + ib));
            s0 += f.x; s1 += f.y;
        }
        swsum[wid][2 * lane] = s0;
        swsum[wid][2 * lane + 1] = s1;
        __syncthreads();

        float p0 = spfx[isK][2 * lane];
        float p1 = spfx[isK][2 * lane + 1];
        for (int w = isK * 4; w < wid; w++) {
            p0 += swsum[w][2 * lane];
            p1 += swsum[w][2 * lane + 1];
        }

        int nbase = ch * CHUNK + blk * 32;
        for (int i = 0; i < 32; i++) {
            int r = blk * 32 + i;
            char* p = tb + r * 128 + ((segc ^ (r & 7)) << 4) + ib;
            float2 f = __half22float2(*(__half2*)p);
            p0 += f.x; p1 += f.y;
            float inv = 1.0f / (float)(nbase + i + 1);
            *(__half2*)p = __floats2half2_rn(p0 * inv, p1 * inv);
        }
    }
    __syncthreads();

    // ---- phase 2b: per-row L2 normalization (one thread/row, two passes) ----
    {
        const int side = tid >> 7;          // 0: q, 1: k
        const int r = tid & 127;
        char* tb = smem + side * 16384 + r * 128;
        const int sx = (r & 7) << 4;
        float nrm = 0.f;
#pragma unroll
        for (int seg = 0; seg < 8; seg++) {
            uint4 v = *(uint4*)(tb + ((seg << 4) ^ sx));
            const __half2* hp = (const __half2*)&v;
#pragma unroll
            for (int j = 0; j < 4; j++) {
                float2 f = __half22float2(hp[j]);
                nrm = fmaf(f.x, f.x, fmaf(f.y, f.y, nrm));
            }
        }
        float rs = 1.0f / fmaxf(sqrtf(nrm), 1e-12f);
#pragma unroll
        for (int seg = 0; seg < 8; seg++) {
            uint4 v = *(uint4*)(tb + ((seg << 4) ^ sx));
            __half2* hp = (__half2*)&v;
#pragma unroll
            for (int j = 0; j < 4; j++) {
                float2 f = __half22float2(hp[j]);
                hp[j] = __floats2half2_rn(f.x * rs, f.y * rs);
            }
            *(uint4*)(tb + ((seg << 4) ^ sx)) = v;
        }
    }
    __syncthreads();

    // ---- mma phase: 8 warps, warp tile 16 rows x 64 cols ----
    const int wm = wid * 16;
    float acc[8][4];
#pragma unroll
    for (int j = 0; j < 8; j++)
#pragma unroll
        for (int e = 0; e < 4; e++) acc[j][e] = 0.0f;

#pragma unroll
    for (int part = 0; part < 2; part++) {
        uint32_t aBase = sbase + part * 16384;
        uint32_t hBase = sbase + 32768 + part * 8192;
#pragma unroll
        for (int ks = 0; ks < 4; ks++) {
            uint32_t a[4], bhf[4][4];
            {
                int arow = wm + (lane & 15);
                int seg = ks * 2 + (lane >> 4);
                ldsm4(a, aBase + arow * 128 + ((seg ^ (arow & 7)) << 4));
            }
#pragma unroll
            for (int ng = 0; ng < 4; ng++) {
                int brow = ng * 16 + ((lane >> 4) << 3) + (lane & 7);
                int seg = ks * 2 + ((lane & 15) >> 3);
                uint32_t off = brow * 128 + ((seg ^ (brow & 7)) << 4);
                ldsm4(bhf[ng], hBase + off);
            }
#pragma unroll
            for (int nf = 0; nf < 8; nf++)
                mma16816(acc[nf], a, &bhf[nf >> 1][(nf & 1) * 2]);
        }
    }

    // ---- epilogue ----
    {
        int s0r = s0base + wm + (lane >> 2);
#pragma unroll
        for (int nf = 0; nf < 8; nf++) {
            int col = nf * 8 + (lane & 3) * 2;
            float b0 = bc[col], b1 = bc[col + 1];
            size_t o0 = ((size_t)(b * SS + s0r)) * FF + h * DKk + col;
            size_t o1 = o0 + (size_t)8 * FF;
            *(__half2*)&g_xh[o0] = __floats2half2_rn(acc[nf][0] + b0, acc[nf][1] + b1);
            *(__half2*)&g_xh[o1] = __floats2half2_rn(acc[nf][2] + b0, acc[nf][3] + b1);
        }
    }
}

// ---------------------------------------------------------------------------
// Launch
// ---------------------------------------------------------------------------
extern "C" void kernel_launch(void* const* d_in, const int* in_sizes, int n_in,
                              void* d_out, int out_size)
{
    const float* query = (const float*)d_in[0];
    const float* key   = (const float*)d_in[1];
    const float* Wq = (const float*)d_in[4];
    const float* bq = (const float*)d_in[5];
    const float* Wk = (const float*)d_in[6];
    const float* bk = (const float*)d_in[7];
    const float* We = (const float*)d_in[10];
    const float* Wr = (const float*)d_in[11];
    const float* Wc = (const float*)d_in[13];
    const float* bc = (const float*)d_in[14];
    const float* Wo = (const float*)d_in[15];
    const float* bo = (const float*)d_in[16];
    float* out = (float*)d_out;

    void *ppq, *ppk, *pqc, *pkc, *pqh, *pkh, *pxh;
    void *pwqh, *pwkh, *pwoh;
    cudaGetSymbolAddress(&ppq, g_pq);
    cudaGetSymbolAddress(&ppk, g_pk);
    cudaGetSymbolAddress(&pqc, g_qc);
    cudaGetSymbolAddress(&pkc, g_kc);
    cudaGetSymbolAddress(&pqh, g_qh);
    cudaGetSymbolAddress(&pkh, g_kh);
    cudaGetSymbolAddress(&pxh, g_xh);
    cudaGetSymbolAddress(&pwqh, g_wqh);
    cudaGetSymbolAddress(&pwkh, g_wkh);
    cudaGetSymbolAddress(&pwoh, g_woh);

    cudaFuncSetAttribute((void*)gemm_hmma<true>,
                         cudaFuncAttributeMaxDynamicSharedMemorySize, GEMM_SMEM);
    cudaFuncSetAttribute((void*)gemm_hmma<false>,
                         cudaFuncAttributeMaxDynamicSharedMemorySize, GEMM_SMEM);
    cudaFuncSetAttribute((void*)xgemm_kernel,
                         cudaFuncAttributeMaxDynamicSharedMemorySize, XG_SMEM);

    // 0. converts (activations + weights, one launch) + make_m (smem-staged)
    cvt_all_kernel<<<CV_TOTAL, 256>>>(query, key, Wq, Wk, Wo);
    make_m_kernel<<<HH, 256>>>(We, Wr, Wc);

    // 1. q + k projections fused in one launch (fp16 out + chunk column sums)
    GemmArgs aq{(const __half*)pqh, (const __half*)pwqh, bq, (__half*)ppq, nullptr, (float*)pqc};
    GemmArgs ak{(const __half*)pkh, (const __half*)pwkh, bk, (__half*)ppk, nullptr, (float*)pkc};
    gemm_hmma<true><<<dim3(FF / Bb_N, MM / Bb_M, 2), 256, GEMM_SMEM>>>(aq, ak);

    // 2. fused chunk-prefix + norm + x = qn@Me + kn@Mr + bc (batched HMMA)
    xgemm_kernel<<<dim3(NCH, BB * HH), 256, XG_SMEM>>>(bc);

    // 3. output projection (single-pass fp16 HMMA, fp32 out, 128x128 tiles)
    GemmArgs ao{(const __half*)pxh, (const __half*)pwoh, bo, nullptr, out, nullptr};
    gemm_hmma<false><<<dim3(FF / Bb_N, MM / Bb_M, 1), 256, GEMM_SMEM>>>(ao, ao);
}

// round 17
// speedup vs baseline: 1.2071x; 1.0016x over previous
#include <cuda_runtime.h>
#include <cuda_fp16.h>
#include <cstdint>

// Problem constants
#define BB 4
#define SS 4096
#define FF 1024
#define HH 16
#define DKk 64
#define RR 32
#define CHUNK 128
#define NCH (SS / CHUNK)   // 32
#define MM (BB * SS)       // 16384

// GEMM tiling
#define Bb_M 128
#define Bb_N 128
#define NCHUNKS (FF / 32)          // 16 K-chunks of 32
#define STG 16384                  // A 8K | B 8K per stage
#define NSTAGES 4
#define GEMM_SMEM (NSTAGES * STG)  // 64 KB

// ---------------------------------------------------------------------------
// Scratch (device globals; no allocation allowed)
// ---------------------------------------------------------------------------
__device__ __half g_pq[MM * FF];   // projected q (fp16)
__device__ __half g_pk[MM * FF];   // projected k (fp16)
__device__ float g_qc[BB * NCH * FF];   // per-chunk column sums (incl bias)
__device__ float g_kc[BB * NCH * FF];
__device__ __half g_qh[MM * FF];   // fp16 query input
__device__ __half g_kh[MM * FF];   // fp16 key input
__device__ __half g_xh[MM * FF];   // pre-output activation (fp16)
__device__ __half g_wqh[FF * FF];
__device__ __half g_wkh[FF * FF];
__device__ __half g_woh[FF * FF];
__device__ __half g_meh[HH * DKk * DKk];
__device__ __half g_mrh[HH * DKk * DKk];

struct GemmArgs {
    const __half* A;
    const __half* B;
    const float* bias;
    __half* Ch;     // used when HALFOUT
    float* Cf;      // used when !HALFOUT
    float* cs;      // optional per-chunk column sums
};

// ---------------------------------------------------------------------------
// PTX helpers (plain sm_80+ instructions: ldmatrix / mma.sync / cp.async)
// ---------------------------------------------------------------------------
__device__ __forceinline__ uint32_t smem_u32(const void* p) {
    uint32_t a;
    asm("{ .reg .u64 t; cvta.to.shared.u64 t, %1; cvt.u32.u64 %0, t; }" : "=r"(a) : "l"(p));
    return a;
}

__device__ __forceinline__ void cpasync16(uint32_t s, const void* g) {
    asm volatile("cp.async.cg.shared.global [%0], [%1], 16;" :: "r"(s), "l"(g));
}
__device__ __forceinline__ void cp_commit() {
    asm volatile("cp.async.commit_group;" ::: "memory");
}
template <int N>
__device__ __forceinline__ void cp_wait() {
    asm volatile("cp.async.wait_group %0;" :: "n"(N) : "memory");
}

__device__ __forceinline__ void ldsm4(uint32_t* r, uint32_t addr) {
    asm volatile("ldmatrix.sync.aligned.m8n8.x4.shared.b16 {%0,%1,%2,%3}, [%4];"
                 : "=r"(r[0]), "=r"(r[1]), "=r"(r[2]), "=r"(r[3]) : "r"(addr));
}

__device__ __forceinline__ void mma16816(float* c, const uint32_t* a, const uint32_t* b) {
    asm volatile(
        "mma.sync.aligned.m16n8k16.row.col.f32.f16.f16.f32 "
        "{%0,%1,%2,%3}, {%4,%5,%6,%7}, {%8,%9}, {%0,%1,%2,%3};"
        : "+f"(c[0]), "+f"(c[1]), "+f"(c[2]), "+f"(c[3])
        : "r"(a[0]), "r"(a[1]), "r"(a[2]), "r"(a[3]), "r"(b[0]), "r"(b[1]));
}

// ---------------------------------------------------------------------------
// All fp32->fp16 converts in ONE launch. Flat-grid job split (compile-time).
// ---------------------------------------------------------------------------
#define CV_ACT (MM * FF / 4 / 256)   // 16384 blocks per activation
#define CV_W   (FF * FF / 4 / 256)   // 1024 blocks per weight
#define CV_TOTAL (2 * CV_ACT + 3 * CV_W)
__global__ void cvt_all_kernel(const float* __restrict__ q, const float* __restrict__ k,
                               const float* __restrict__ wq, const float* __restrict__ wk,
                               const float* __restrict__ wo)
{
    int bidx = blockIdx.x;
    const float* src; __half* dst; int i0;
    if (bidx < CV_ACT)                     { src = q;  dst = g_qh;  i0 = bidx; }
    else if (bidx < 2 * CV_ACT)            { src = k;  dst = g_kh;  i0 = bidx - CV_ACT; }
    else if (bidx < 2 * CV_ACT + CV_W)     { src = wq; dst = g_wqh; i0 = bidx - 2 * CV_ACT; }
    else if (bidx < 2 * CV_ACT + 2 * CV_W) { src = wk; dst = g_wkh; i0 = bidx - 2 * CV_ACT - CV_W; }
    else                                   { src = wo; dst = g_woh; i0 = bidx - 2 * CV_ACT - 2 * CV_W; }
    int i = i0 * 256 + threadIdx.x;
    float4 v = ((const float4*)src)[i];
    ((__half2*)dst)[2 * i]     = __floats2half2_rn(v.x, v.y);
    ((__half2*)dst)[2 * i + 1] = __floats2half2_rn(v.z, v.w);
}

// ---------------------------------------------------------------------------
// Precompute per-head Me = We@Wc1^T, Mr = Wr@Wc2^T (stored [n][k], fp16 hi)
// ---------------------------------------------------------------------------
__global__ void make_m_kernel(const float* __restrict__ We, const float* __restrict__ Wr,
                              const float* __restrict__ Wc)
{
    int h = blockIdx.x;
    __shared__ float sWe[DKk * RR], sWr[DKk * RR], sWc[DKk * 2 * RR];
    for (int i = threadIdx.x; i < DKk * RR; i += 256) {
        sWe[i] = We[h * DKk * RR + i];
        sWr[i] = Wr[h * DKk * RR + i];
    }
    for (int i = threadIdx.x; i < DKk * 2 * RR; i += 256) sWc[i] = Wc[i];
    __syncthreads();
    for (int idx = threadIdx.x; idx < DKk * DKk; idx += 256) {
        int n = idx >> 6, kk = idx & 63;
        float me = 0.f, mr = 0.f;
#pragma unroll
        for (int e = 0; e < RR; e++) {
            me += sWe[kk * RR + e] * sWc[n * (2 * RR) + e];
            mr += sWr[kk * RR + e] * sWc[n * (2 * RR) + RR + e];
        }
        g_meh[h * 4096 + idx] = __float2half_rn(me);
        g_mrh[h * 4096 + idx] = __float2half_rn(mr);
    }
}

// ---------------------------------------------------------------------------
// HMMA GEMM: C[m,n] = bias[n] + sum_k A[m,k]*B[n,k], single fp16 pass.
// 128x128 tile, K chunks of 32, 4-stage cp.async pipe, 2 CTAs/SM.
// blockIdx.z selects arg set (fused q/k launch). HALFOUT: write fp16.
// Optional colsum: per-128-row-chunk column sums of final C (incl bias).
// ---------------------------------------------------------------------------
template <bool HALFOUT>
__global__ __launch_bounds__(256, 2)
void gemm_hmma(GemmArgs g0, GemmArgs g1)
{
    const GemmArgs g = blockIdx.z ? g1 : g0;
    extern __shared__ char smem[];
    __shared__ float scs[2][128];
    const uint32_t sbase = smem_u32(smem);
    const int tid = threadIdx.x;
    const int wid = tid >> 5, lane = tid & 31;
    const int m0 = blockIdx.y * Bb_M;
    const int n0 = blockIdx.x * Bb_N;
    const int wm = (wid & 1) * 64;
    const int wn = (wid >> 1) * 32;

    const char* pA = (const char*)g.A + (size_t)m0 * (FF * 2);
    const char* pB = (const char*)g.B + (size_t)n0 * (FF * 2);

    const int lrow0 = tid >> 2;
    const int lseg = tid & 3;

    auto load_stage = [&](int c, int buf) {
        uint32_t sb = sbase + buf * STG;
        size_t kb = (size_t)c * 64;
#pragma unroll
        for (int i = 0; i < 2; i++) {
            int row = lrow0 + i * 64;
            uint32_t soff = row * 64 + ((lseg ^ ((row >> 1) & 3)) << 4);
            size_t goff = (size_t)row * (FF * 2) + kb + lseg * 16;
            cpasync16(sb + soff,        pA + goff);
            cpasync16(sb + 8192 + soff, pB + goff);
        }
        cp_commit();
    };

    float acc[4][4][4];
#pragma unroll
    for (int i = 0; i < 4; i++)
#pragma unroll
        for (int j = 0; j < 4; j++)
#pragma unroll
            for (int e = 0; e < 4; e++) acc[i][j][e] = 0.0f;

    int arow[4]; uint32_t aoffbase[4];
#pragma unroll
    for (int mf = 0; mf < 4; mf++) {
        arow[mf] = wm + mf * 16 + (lane & 15);
        aoffbase[mf] = arow[mf] * 64;
    }
    int brow[2];
#pragma unroll
    for (int ng = 0; ng < 2; ng++)
        brow[ng] = wn + ng * 16 + ((lane >> 4) << 3) + (lane & 7);

    load_stage(0, 0);
    load_stage(1, 1);
    load_stage(2, 2);

    for (int c = 0; c < NCHUNKS; c++) {
        if (c + 2 < NCHUNKS) cp_wait<2>();
        else if (c + 1 < NCHUNKS) cp_wait<1>();
        else cp_wait<0>();
        __syncthreads();
        if (c + 3 < NCHUNKS) load_stage(c + 3, (c + 3) % NSTAGES);

        uint32_t sb = sbase + (c % NSTAGES) * STG;
#pragma unroll
        for (int ks = 0; ks < 2; ks++) {
            uint32_t ah[4][4], bf[2][4];
#pragma unroll
            for (int mf = 0; mf < 4; mf++) {
                int seg = ks * 2 + (lane >> 4);
                uint32_t off = aoffbase[mf] + ((seg ^ ((arow[mf] >> 1) & 3)) << 4);
                ldsm4(ah[mf], sb + off);
            }
#pragma unroll
            for (int ng = 0; ng < 2; ng++) {
                int seg = ks * 2 + ((lane & 15) >> 3);
                uint32_t off = brow[ng] * 64 + ((seg ^ ((brow[ng] >> 1) & 3)) << 4);
                ldsm4(bf[ng], sb + 8192 + off);
            }
#pragma unroll
            for (int mf = 0; mf < 4; mf++)
#pragma unroll
                for (int nf = 0; nf < 4; nf++)
                    mma16816(acc[mf][nf], ah[mf], &bf[nf >> 1][(nf & 1) * 2]);
        }
    }

    // Epilogue: + bias, store (fp16 or fp32)
#pragma unroll
    for (int mf = 0; mf < 4; mf++) {
        int r0 = m0 + wm + mf * 16 + (lane >> 2);
#pragma unroll
        for (int nf = 0; nf < 4; nf++) {
            int col = n0 + wn + nf * 8 + (lane & 3) * 2;
            float bx = g.bias[col], by = g.bias[col + 1];
            float v00 = acc[mf][nf][0] + bx, v01 = acc[mf][nf][1] + by;
            float v10 = acc[mf][nf][2] + bx, v11 = acc[mf][nf][3] + by;
            if (HALFOUT) {
                *(__half2*)&g.Ch[(size_t)r0 * FF + col]       = __floats2half2_rn(v00, v01);
                *(__half2*)&g.Ch[(size_t)(r0 + 8) * FF + col] = __floats2half2_rn(v10, v11);
            } else {
                *(float2*)&g.Cf[(size_t)r0 * FF + col]       = make_float2(v00, v01);
                *(float2*)&g.Cf[(size_t)(r0 + 8) * FF + col] = make_float2(v10, v11);
            }
        }
    }

    // Optional: per-chunk column sums (this CTA's 128 rows == one (b,chunk))
    if (g.cs != nullptr) {
        float cs0[4], cs1[4];
#pragma unroll
        for (int nf = 0; nf < 4; nf++) {
            cs0[nf] = 0.f; cs1[nf] = 0.f;
#pragma unroll
            for (int mf = 0; mf < 4; mf++) {
                cs0[nf] += acc[mf][nf][0] + acc[mf][nf][2];
                cs1[nf] += acc[mf][nf][1] + acc[mf][nf][3];
            }
        }
#pragma unroll
        for (int o = 16; o >= 4; o >>= 1)
#pragma unroll
            for (int nf = 0; nf < 4; nf++) {
                cs0[nf] += __shfl_xor_sync(0xffffffffu, cs0[nf], o);
                cs1[nf] += __shfl_xor_sync(0xffffffffu, cs1[nf], o);
            }
        if (lane < 4) {
#pragma unroll
            for (int nf = 0; nf < 4; nf++) {
                scs[wid & 1][wn + nf * 8 + lane * 2]     = cs0[nf];
                scs[wid & 1][wn + nf * 8 + lane * 2 + 1] = cs1[nf];
            }
        }
        __syncthreads();
        if (tid < 128) {
            float tot = scs[0][tid] + scs[1][tid] + 128.0f * g.bias[n0 + tid];
            g.cs[(m0 >> 7) * FF + n0 + tid] = tot;
        }
    }
}

// ---------------------------------------------------------------------------
// Fused scan + norm + xgemm: per (b,h,chunk=128 rows). 4 CTAs/SM.
//   0. (overlapped with loads) sum chunk colsums 0..ch-1 -> smem prefix
//   1. load pq/pk tile (fp16) + Me/Mr into smem via cp.async
//   2a. serial cumsum + running-average in smem (shfl-free)
//   2b. per-ROW norm factor rs only (one thread/row, read pass, NO write-back)
//   3. x = (qa·rs_q)@Me + (ka·rs_k)@Mr + bc via HMMA, scaling the A
//      fragments in registers (2 broadcast LDS + 4 HMUL2 per ldsm); fp16 x.
// 256 threads. SMEM: sQ 16K | sK 16K | Me 8K | Mr 8K = 48KB.
// ---------------------------------------------------------------------------
#define XG_SMEM 49152
__global__ __launch_bounds__(256, 4)
void xgemm_kernel(const float* __restrict__ bc)
{
    extern __shared__ char smem[];
    __shared__ float swsum[8][64];
    __shared__ float spfx[2][64];
    __shared__ __half rs_h[2][128];
    const uint32_t sbase = smem_u32(smem);
    const int tid = threadIdx.x;
    const int wid = tid >> 5, lane = tid & 31;
    const int ch = blockIdx.x;
    const int s0base = ch * 128;
    const int b = blockIdx.y >> 4;
    const int h = blockIdx.y & 15;

    // ---- load phase (async) ----
    {
        const char* gq = (const char*)g_pq + (((size_t)(b * SS + s0base)) * FF + h * DKk) * 2;
        const char* gk = (const char*)g_pk + (((size_t)(b * SS + s0base)) * FF + h * DKk) * 2;
        int row = tid >> 1;                 // 0..127
        int sh = (tid & 1) * 4;
#pragma unroll
        for (int s = 0; s < 4; s++) {
            int seg = sh + s;
            uint32_t soff = row * 128 + ((seg ^ (row & 7)) << 4);
            size_t goff = (size_t)row * (FF * 2) + seg * 16;
            cpasync16(sbase + soff,         gq + goff);
            cpasync16(sbase + 16384 + soff, gk + goff);
        }
        const char* srcs[2] = {(const char*)(g_meh + h * 4096), (const char*)(g_mrh + h * 4096)};
#pragma unroll
        for (int j = 0; j < 4; j++) {
            int i = tid + j * 256;          // 0..1023
            int m = i >> 9;
            int r = (i >> 3) & 63;
            int seg = i & 7;
            uint32_t soff = r * 128 + ((seg ^ (r & 7)) << 4);
            cpasync16(sbase + 32768 + m * 8192 + soff, srcs[m] + r * 128 + seg * 16);
        }
        cp_commit();
    }

    // ---- phase 0 (overlapped): chunk prefix from colsums ----
    if (tid < 128) {
        int side = tid >> 6;            // 0: q, 1: k
        int col = tid & 63;
        const float* pc = side ? g_kc : g_qc;
        float s = 0.f;
#pragma unroll 8
        for (int c = 0; c < ch; c++)
            s += pc[(b * NCH + c) * FF + h * DKk + col];
        spfx[side][col] = s;
    }

    cp_wait<0>();
    __syncthreads();

    // ---- phase 2a: serial cumsum + running average (shfl-free) ----
    {
        const int isK = wid >> 2;           // warps 0-3: q, 4-7: k
        const int blk = wid & 3;            // 32-row sub-block
        char* tb = smem + isK * 16384;
        const int segc = lane >> 2;
        const int ib = (lane & 3) * 4;

        float s0 = 0.f, s1 = 0.f;
#pragma unroll 8
        for (int i = 0; i < 32; i++) {
            int r = blk * 32 + i;
            float2 f = __half22float2(*(__half2*)(tb + r * 128 + ((segc ^ (r & 7)) << 4) + ib));
            s0 += f.x; s1 += f.y;
        }
        swsum[wid][2 * lane] = s0;
        swsum[wid][2 * lane + 1] = s1;
        __syncthreads();

        float p0 = spfx[isK][2 * lane];
        float p1 = spfx[isK][2 * lane + 1];
        for (int w = isK * 4; w < wid; w++) {
            p0 += swsum[w][2 * lane];
            p1 += swsum[w][2 * lane + 1];
        }

        int nbase = ch * CHUNK + blk * 32;
        for (int i = 0; i < 32; i++) {
            int r = blk * 32 + i;
            char* p = tb + r * 128 + ((segc ^ (r & 7)) << 4) + ib;
            float2 f = __half22float2(*(__half2*)p);
            p0 += f.x; p1 += f.y;
            float inv = 1.0f / (float)(nbase + i + 1);
            *(__half2*)p = __floats2half2_rn(p0 * inv, p1 * inv);
        }
    }
    __syncthreads();

    // ---- phase 2b: per-row inverse norm only (one thread/row, no write-back) ----
    {
        const int side = tid >> 7;          // 0: q, 1: k
        const int r = tid & 127;
        char* tb = smem + side * 16384 + r * 128;
        const int sx = (r & 7) << 4;
        float nrm = 0.f;
#pragma unroll
        for (int seg = 0; seg < 8; seg++) {
            uint4 v = *(uint4*)(tb + ((seg << 4) ^ sx));
            const __half2* hp = (const __half2*)&v;
#pragma unroll
            for (int j = 0; j < 4; j++) {
                float2 f = __half22float2(hp[j]);
                nrm = fmaf(f.x, f.x, fmaf(f.y, f.y, nrm));
            }
        }
        float rs = 1.0f / fmaxf(sqrtf(nrm), 1e-12f);
        rs_h[side][r] = __float2half_rn(rs);
    }
    __syncthreads();

    // ---- mma phase: 8 warps, warp tile 16 rows x 64 cols; A scaled by rs ----
    const int wm = wid * 16;
    float acc[8][4];
#pragma unroll
    for (int j = 0; j < 8; j++)
#pragma unroll
        for (int e = 0; e < 4; e++) acc[j][e] = 0.0f;

#pragma unroll
    for (int part = 0; part < 2; part++) {
        uint32_t aBase = sbase + part * 16384;
        uint32_t hBase = sbase + 32768 + part * 8192;
        // per-thread row scales for this side (a0/a2 row, a1/a3 row)
        __half2 s_lo = __half2half2(rs_h[part][wm + (lane >> 2)]);
        __half2 s_hi = __half2half2(rs_h[part][wm + (lane >> 2) + 8]);
#pragma unroll
        for (int ks = 0; ks < 4; ks++) {
            uint32_t a[4], bhf[4][4];
            {
                int arow = wm + (lane & 15);
                int seg = ks * 2 + (lane >> 4);
                ldsm4(a, aBase + arow * 128 + ((seg ^ (arow & 7)) << 4));
                *(__half2*)&a[0] = __hmul2(*(__half2*)&a[0], s_lo);
                *(__half2*)&a[1] = __hmul2(*(__half2*)&a[1], s_hi);
                *(__half2*)&a[2] = __hmul2(*(__half2*)&a[2], s_lo);
                *(__half2*)&a[3] = __hmul2(*(__half2*)&a[3], s_hi);
            }
#pragma unroll
            for (int ng = 0; ng < 4; ng++) {
                int brow = ng * 16 + ((lane >> 4) << 3) + (lane & 7);
                int seg = ks * 2 + ((lane & 15) >> 3);
                uint32_t off = brow * 128 + ((seg ^ (brow & 7)) << 4);
                ldsm4(bhf[ng], hBase + off);
            }
#pragma unroll
            for (int nf = 0; nf < 8; nf++)
                mma16816(acc[nf], a, &bhf[nf >> 1][(nf & 1) * 2]);
        }
    }

    // ---- epilogue ----
    {
        int s0r = s0base + wm + (lane >> 2);
#pragma unroll
        for (int nf = 0; nf < 8; nf++) {
            int col = nf * 8 + (lane & 3) * 2;
            float b0 = bc[col], b1 = bc[col + 1];
            size_t o0 = ((size_t)(b * SS + s0r)) * FF + h * DKk + col;
            size_t o1 = o0 + (size_t)8 * FF;
            *(__half2*)&g_xh[o0] = __floats2half2_rn(acc[nf][0] + b0, acc[nf][1] + b1);
            *(__half2*)&g_xh[o1] = __floats2half2_rn(acc[nf][2] + b0, acc[nf][3] + b1);
        }
    }
}

// ---------------------------------------------------------------------------
// Launch
// ---------------------------------------------------------------------------
extern "C" void kernel_launch(void* const* d_in, const int* in_sizes, int n_in,
                              void* d_out, int out_size)
{
    const float* query = (const float*)d_in[0];
    const float* key   = (const float*)d_in[1];
    const float* Wq = (const float*)d_in[4];
    const float* bq = (const float*)d_in[5];
    const float* Wk = (const float*)d_in[6];
    const float* bk = (const float*)d_in[7];
    const float* We = (const float*)d_in[10];
    const float* Wr = (const float*)d_in[11];
    const float* Wc = (const float*)d_in[13];
    const float* bc = (const float*)d_in[14];
    const float* Wo = (const float*)d_in[15];
    const float* bo = (const float*)d_in[16];
    float* out = (float*)d_out;

    void *ppq, *ppk, *pqc, *pkc, *pqh, *pkh, *pxh;
    void *pwqh, *pwkh, *pwoh;
    cudaGetSymbolAddress(&ppq, g_pq);
    cudaGetSymbolAddress(&ppk, g_pk);
    cudaGetSymbolAddress(&pqc, g_qc);
    cudaGetSymbolAddress(&pkc, g_kc);
    cudaGetSymbolAddress(&pqh, g_qh);
    cudaGetSymbolAddress(&pkh, g_kh);
    cudaGetSymbolAddress(&pxh, g_xh);
    cudaGetSymbolAddress(&pwqh, g_wqh);
    cudaGetSymbolAddress(&pwkh, g_wkh);
    cudaGetSymbolAddress(&pwoh, g_woh);

    cudaFuncSetAttribute((void*)gemm_hmma<true>,
                         cudaFuncAttributeMaxDynamicSharedMemorySize, GEMM_SMEM);
    cudaFuncSetAttribute((void*)gemm_hmma<false>,
                         cudaFuncAttributeMaxDynamicSharedMemorySize, GEMM_SMEM);
    cudaFuncSetAttribute((void*)xgemm_kernel,
                         cudaFuncAttributeMaxDynamicSharedMemorySize, XG_SMEM);

    // 0. converts (activations + weights, one launch) + make_m (smem-staged)
    cvt_all_kernel<<<CV_TOTAL, 256>>>(query, key, Wq, Wk, Wo);
    make_m_kernel<<<HH, 256>>>(We, Wr, Wc);

    // 1. q + k projections fused in one launch (fp16 out + chunk column sums)
    GemmArgs aq{(const __half*)pqh, (const __half*)pwqh, bq, (__half*)ppq, nullptr, (float*)pqc};
    GemmArgs ak{(const __half*)pkh, (const __half*)pwkh, bk, (__half*)ppk, nullptr, (float*)pkc};
    gemm_hmma<true><<<dim3(FF / Bb_N, MM / Bb_M, 2), 256, GEMM_SMEM>>>(aq, ak);

    // 2. fused chunk-prefix + norm + x = qn@Me + kn@Mr + bc (batched HMMA)
    xgemm_kernel<<<dim3(NCH, BB * HH), 256, XG_SMEM>>>(bc);

    // 3. output projection (single-pass fp16 HMMA, fp32 out, 128x128 tiles)
    GemmArgs ao{(const __half*)pxh, (const __half*)pwoh, bo, nullptr, out, nullptr};
    gemm_hmma<false><<<dim3(FF / Bb_N, MM / Bb_M, 1), 256, GEMM_SMEM>>>(ao, ao);
}